// round 11
// baseline (speedup 1.0000x reference)
#include <cuda_runtime.h>
#include <cuda_bf16.h>
#include <math.h>
#include <stdint.h>

#define H_IMG 200
#define W_IMG 200
#define HW    40000
#define C1    64
#define C3    256
#define NHEADS 8
#define HD    32
#define BSZ   2
#define CF    1024
#define ATT_SCALE 0.17677669529663687f   // 32^-0.5

// ---------------- static scratch ----------------
__device__ float           g_Q [BSZ * C3 * HW];          // NCHW fp32
__device__ __nv_bfloat162  g_K2[BSZ * (C3 / 2) * HW];    // [cpair][HW] packed bf16
__device__ __nv_bfloat162  g_V2[BSZ * (C3 / 2) * HW];
__device__ float g_AO [BSZ * HW * C3];   // NHWC
__device__ float g_X  [BSZ * HW * C3];   // NHWC
__device__ float g_Y  [BSZ * HW * C3];   // NHWC
__device__ float g_Hid[BSZ * HW * CF];

__device__ __forceinline__ float f2tf(float x) {
    uint32_t u;
    asm("cvt.rna.tf32.f32 %0, %1;" : "=r"(u) : "f"(x));
    return __uint_as_float(u);
}

// ---------------- f32x2 packed-math helpers ----------------
__device__ __forceinline__ uint64_t pk2(float lo, float hi) {
    uint64_t r;
    asm("mov.b64 %0, {%1, %2};" : "=l"(r) : "f"(lo), "f"(hi));
    return r;
}
__device__ __forceinline__ void upk2(uint64_t v, float& lo, float& hi) {
    asm("mov.b64 {%0, %1}, %2;" : "=f"(lo), "=f"(hi) : "l"(v));
}
__device__ __forceinline__ uint64_t fma2(uint64_t a, uint64_t b, uint64_t c) {
    uint64_t d;
    asm("fma.rn.f32x2 %0, %1, %2, %3;" : "=l"(d) : "l"(a), "l"(b), "l"(c));
    return d;
}
__device__ __forceinline__ uint64_t bf2_to_f2(uint32_t kv) {
    return pk2(__uint_as_float(kv << 16), __uint_as_float(kv & 0xFFFF0000u));
}

// ---------------- GEMM smem layout ----------------
// Both A and B k-interleaved: elem (k, r) at [ (k%4)*PLANE + 4*r + k/4 ].
// One LDS.128 at (tg, r) -> k = {tg, tg+4, tg+8, tg+12}: frags for both kk steps.
#define APL 1032             // plane stride A: 4*256 + 8
#define BPL 520              // plane stride B: 4*128 + 8
#define ABUF2 (4 * APL)      // 4128 floats
#define BBUF2 (4 * BPL)      // 2080 floats
#define SBUF2 (ABUF2 + BBUF2)            // per stage, floats
#define GSMEM (2 * SBUF2 * 4)            // bytes = 49664

// ---------------- tf32 tensor-core GEMM, BM=256 BN=128 BK=16, 8 warps 64x64 ----
// TA=0: A row-major [M,K]. TA=1: A stored [K,M] (row stride M).
// TB=0: B row-major [K,N]. TB=1: B stored [N,K] (B^T used).
// PACKBF: C written as packed bf16 pairs [(m/2)][n], cStr in bf16 elements.
template<int TA, int TB, int ACCU, int RELU, int BIAS, int PACKBF>
__global__ __launch_bounds__(256) void gemm_tc(
    const float* __restrict__ A, const float* __restrict__ B,
    const float* __restrict__ bias, float* __restrict__ C,
    int M, int N, int K, long aStr, long bStr, long cStr)
{
    extern __shared__ __align__(16) float smd[];
    A += (long)blockIdx.z * aStr;
    B += (long)blockIdx.z * bStr;
    __nv_bfloat16* cb = (__nv_bfloat16*)C + (long)blockIdx.z * cStr;  // PACKBF path
    if (!PACKBF) C += (long)blockIdx.z * cStr;

    const int m0 = blockIdx.y * 256;
    const int n0 = blockIdx.x * 128;
    const int t    = threadIdx.x;
    const int lane = t & 31, w = t >> 5;
    const int g  = lane >> 2, tg = lane & 3;
    const int wm = (w & 3) * 64, wn = (w >> 2) * 64;

    float acc[4][8][4];
#pragma unroll
    for (int i = 0; i < 4; i++)
#pragma unroll
        for (int j = 0; j < 8; j++)
#pragma unroll
            for (int r = 0; r < 4; r++) acc[i][j][r] = 0.f;

    float ra[4][4], rb[2][4];

    auto loadA = [&](int k0) {
        if (TA == 0) {
#pragma unroll
            for (int v = 0; v < 4; v++) {
                int idx = t + v * 256;
                int row = idx >> 2, j = idx & 3;
                bool ok = (m0 + row) < M;
                float4 q = make_float4(0.f, 0.f, 0.f, 0.f);
                if (ok) q = *(const float4*)(A + (long)(m0 + row) * K + k0 + 4 * j);
                ra[v][0] = q.x; ra[v][1] = q.y; ra[v][2] = q.z; ra[v][3] = q.w;
            }
        } else {
            int k4 = t & 3, mb = t >> 2;
#pragma unroll
            for (int o = 0; o < 4; o++) {
                int m = mb + 64 * o;
                bool ok = (m0 + m) < M;
                const float* p = A + (long)(k0 + 4 * k4) * M + (ok ? m0 + m : 0);
#pragma unroll
                for (int i = 0; i < 4; i++)
                    ra[o][i] = ok ? p[(long)i * M] : 0.f;
            }
        }
    };
    auto loadB = [&](int k0) {
        int k4 = t & 3;
#pragma unroll
        for (int v = 0; v < 2; v++) {
            int n = (t >> 2) + 64 * v;
            bool ok = (n0 + n) < N;
            if (TB == 0) {
                const float* p = B + (long)(k0 + 4 * k4) * N + (ok ? n0 + n : 0);
#pragma unroll
                for (int i = 0; i < 4; i++)
                    rb[v][i] = ok ? p[(long)i * N] : 0.f;
            } else {
                float4 q = make_float4(0.f, 0.f, 0.f, 0.f);
                if (ok) q = *(const float4*)(B + (long)(n0 + n) * K + k0 + 4 * k4);
                rb[v][0] = q.x; rb[v][1] = q.y; rb[v][2] = q.z; rb[v][3] = q.w;
            }
        }
    };
    auto storeAB = [&](int s) {
        float* As = smd + s * SBUF2;
        float* Bs = As + ABUF2;
        if (TA == 0) {
#pragma unroll
            for (int v = 0; v < 4; v++) {
                int idx = t + v * 256;
                int row = idx >> 2, j = idx & 3;
#pragma unroll
                for (int i = 0; i < 4; i++)              // k = 4j + i
                    As[APL * i + 4 * row + j] = f2tf(ra[v][i]);
            }
        } else {
            int k4 = t & 3, mb = t >> 2;
#pragma unroll
            for (int o = 0; o < 4; o++) {
                int m = mb + 64 * o;
#pragma unroll
                for (int i = 0; i < 4; i++)              // k = 4k4 + i
                    As[APL * i + 4 * m + k4] = f2tf(ra[o][i]);
            }
        }
        {
            int k4 = t & 3;
#pragma unroll
            for (int v = 0; v < 2; v++) {
                int n = (t >> 2) + 64 * v;
#pragma unroll
                for (int i = 0; i < 4; i++)              // k = 4k4 + i
                    Bs[BPL * i + 4 * n + k4] = f2tf(rb[v][i]);
            }
        }
    };
    auto compute = [&](int s) {
        const float* As = smd + s * SBUF2;
        const float* Bs = As + ABUF2;
        float4 bq[8];
#pragma unroll
        for (int ns = 0; ns < 8; ns++)
            bq[ns] = *(const float4*)&Bs[BPL * tg + 4 * (wn + 8 * ns + g)];
#pragma unroll
        for (int ms = 0; ms < 4; ms++) {
            int m = wm + 16 * ms + g;
            float4 alo = *(const float4*)&As[APL * tg + 4 * m];
            float4 ahi = *(const float4*)&As[APL * tg + 4 * (m + 8)];
#pragma unroll
            for (int ns = 0; ns < 8; ns++) {
                asm volatile(
                    "mma.sync.aligned.m16n8k8.row.col.f32.tf32.tf32.f32 "
                    "{%0,%1,%2,%3}, {%4,%5,%6,%7}, {%8,%9}, {%0,%1,%2,%3};\n"
                    : "+f"(acc[ms][ns][0]), "+f"(acc[ms][ns][1]),
                      "+f"(acc[ms][ns][2]), "+f"(acc[ms][ns][3])
                    : "r"(__float_as_uint(alo.x)), "r"(__float_as_uint(ahi.x)),
                      "r"(__float_as_uint(alo.y)), "r"(__float_as_uint(ahi.y)),
                      "r"(__float_as_uint(bq[ns].x)), "r"(__float_as_uint(bq[ns].y)));
                asm volatile(
                    "mma.sync.aligned.m16n8k8.row.col.f32.tf32.tf32.f32 "
                    "{%0,%1,%2,%3}, {%4,%5,%6,%7}, {%8,%9}, {%0,%1,%2,%3};\n"
                    : "+f"(acc[ms][ns][0]), "+f"(acc[ms][ns][1]),
                      "+f"(acc[ms][ns][2]), "+f"(acc[ms][ns][3])
                    : "r"(__float_as_uint(alo.z)), "r"(__float_as_uint(ahi.z)),
                      "r"(__float_as_uint(alo.w)), "r"(__float_as_uint(ahi.w)),
                      "r"(__float_as_uint(bq[ns].z)), "r"(__float_as_uint(bq[ns].w)));
            }
        }
    };

    const int ktiles = K >> 4;
    loadA(0); loadB(0);
    storeAB(0);
    __syncthreads();
    for (int kt = 0; kt < ktiles; kt++) {
        int buf = kt & 1;
        if (kt + 1 < ktiles) { loadA((kt + 1) << 4); loadB((kt + 1) << 4); }
        compute(buf);
        if (kt + 1 < ktiles) storeAB(buf ^ 1);
        __syncthreads();
    }

    // epilogue
#pragma unroll
    for (int ms = 0; ms < 4; ms++) {
#pragma unroll
        for (int ns = 0; ns < 8; ns++) {
            int ncol = n0 + wn + ns * 8 + tg * 2;
            if (ncol >= N) continue;
            int mrow = m0 + wm + ms * 16 + g;
#pragma unroll
            for (int r = 0; r < 2; r++) {
                int m = mrow + r * 8;
                if (m >= M) continue;
                float v0 = acc[ms][ns][r * 2];
                float v1 = acc[ms][ns][r * 2 + 1];
                if (PACKBF) {
                    long base = ((long)(m >> 1) * N + ncol) * 2 + (m & 1);
                    cb[base]     = __float2bfloat16(v0);
                    cb[base + 2] = __float2bfloat16(v1);
                } else {
                    if (BIAS) { v0 += bias[ncol]; v1 += bias[ncol + 1]; }
                    if (RELU) { v0 = fmaxf(v0, 0.f); v1 = fmaxf(v1, 0.f); }
                    float2* p = (float2*)(C + (long)m * N + ncol);
                    if (ACCU) { float2 o = *p; v0 += o.x; v1 += o.y; }
                    *p = make_float2(v0, v1);
                }
            }
        }
    }
}

// ---------------- 7x7 local-window attention, two-phase + f32x2 ----------------
__global__ __launch_bounds__(128) void attn_kernel(
    const float* __restrict__ Q, const __nv_bfloat162* __restrict__ K,
    const __nv_bfloat162* __restrict__ V, float* __restrict__ O)
{
    __shared__ float sc[128][49];
    const int b = blockIdx.z, nh = blockIdx.y;
    const int t = threadIdx.x;
    const int hw = blockIdx.x * 128 + t;
    if (hw >= HW) return;
    const int h = hw / W_IMG, w = hw % W_IMG;

    const int cbase = (b * C3 + nh * HD) * HW;
    const long kvbase = ((long)b * (C3 / 2) + nh * (HD / 2)) * HW;
    const uint32_t* kb = (const uint32_t*)(K + kvbase);
    const uint32_t* vb = (const uint32_t*)(V + kvbase);

    uint64_t q2[HD / 2];
#pragma unroll
    for (int dp = 0; dp < HD / 2; dp++)
        q2[dp] = pk2(Q[cbase + (2 * dp) * HW + hw], Q[cbase + (2 * dp + 1) * HW + hw]);

    float mx = -1e30f;
    {
        int o = 0;
        for (int i = 0; i < 7; i++) {
            int hh = min(max(h + i - 3, 0), H_IMG - 1);
            int rbase = hh * W_IMG;
#pragma unroll
            for (int j = 0; j < 7; j++) {
                int ww = min(max(w + j - 3, 0), W_IMG - 1);
                int off = rbase + ww;
                uint64_t s2 = pk2(0.f, 0.f);
#pragma unroll
                for (int dp = 0; dp < HD / 2; dp++)
                    s2 = fma2(q2[dp], bf2_to_f2(kb[dp * HW + off]), s2);
                float a, c;
                upk2(s2, a, c);
                float s = (a + c) * ATT_SCALE;
                mx = fmaxf(mx, s);
                sc[t][o++] = s;
            }
        }
    }

    float l = 0.f;
    uint64_t acc2[HD / 2];
#pragma unroll
    for (int dp = 0; dp < HD / 2; dp++) acc2[dp] = pk2(0.f, 0.f);
    {
        int o = 0;
        for (int i = 0; i < 7; i++) {
            int hh = min(max(h + i - 3, 0), H_IMG - 1);
            int rbase = hh * W_IMG;
#pragma unroll
            for (int j = 0; j < 7; j++) {
                int ww = min(max(w + j - 3, 0), W_IMG - 1);
                int off = rbase + ww;
                float p = __expf(sc[t][o++] - mx);
                l += p;
                uint64_t p2 = pk2(p, p);
#pragma unroll
                for (int dp = 0; dp < HD / 2; dp++)
                    acc2[dp] = fma2(bf2_to_f2(vb[dp * HW + off]), p2, acc2[dp]);
            }
        }
    }
    float inv = 1.f / l;
    float* ob = O + ((long)(b * HW + hw)) * C3 + nh * HD;   // NHWC
#pragma unroll
    for (int dp = 0; dp < HD / 2; dp += 2) {
        float a0, a1, a2, a3;
        upk2(acc2[dp], a0, a1);
        upk2(acc2[dp + 1], a2, a3);
        *(float4*)(ob + 2 * dp) = make_float4(a0 * inv, a1 * inv, a2 * inv, a3 * inv);
    }
}

// ---------------- warp-per-pixel LayerNorm (in place, NHWC) --------
__global__ __launch_bounds__(256) void ln_kernel(
    float* __restrict__ X, const float* __restrict__ g, const float* __restrict__ bta,
    int npix)
{
    int wrp  = (blockIdx.x * blockDim.x + threadIdx.x) >> 5;
    int lane = threadIdx.x & 31;
    if (wrp >= npix) return;
    float* xp = X + (long)wrp * C3 + lane * 8;
    float4 v0 = *(float4*)xp;
    float4 v1 = *(float4*)(xp + 4);
    float s  = v0.x + v0.y + v0.z + v0.w + v1.x + v1.y + v1.z + v1.w;
    float ss = v0.x*v0.x + v0.y*v0.y + v0.z*v0.z + v0.w*v0.w
             + v1.x*v1.x + v1.y*v1.y + v1.z*v1.z + v1.w*v1.w;
#pragma unroll
    for (int o = 16; o; o >>= 1) {
        s  += __shfl_xor_sync(0xffffffffu, s,  o);
        ss += __shfl_xor_sync(0xffffffffu, ss, o);
    }
    float mu = s * (1.f / C3);
    float r  = rsqrtf(ss * (1.f / C3) - mu * mu + 1e-5f);
    const float* gp = g   + lane * 8;
    const float* bp = bta + lane * 8;
    float vv[8] = {v0.x, v0.y, v0.z, v0.w, v1.x, v1.y, v1.z, v1.w};
#pragma unroll
    for (int u = 0; u < 8; u++) vv[u] = (vv[u] - mu) * r * gp[u] + bp[u];
    *(float4*)xp       = make_float4(vv[0], vv[1], vv[2], vv[3]);
    *(float4*)(xp + 4) = make_float4(vv[4], vv[5], vv[6], vv[7]);
}

// ---------------- x = LN2(x + y), NHWC -> NCHW output ----------------
__global__ __launch_bounds__(256) void final_kernel(
    const float* __restrict__ X, const float* __restrict__ Y,
    const float* __restrict__ g, const float* __restrict__ bta,
    float* __restrict__ out)
{
    __shared__ float sm[32][264];
    const int b  = blockIdx.y;
    const int p0 = blockIdx.x * 32;
    const int t = threadIdx.x, lane = t & 31, wid = t >> 5;

    for (int qq = 0; qq < 4; qq++) {
        int px = wid * 4 + qq;
        long base = ((long)b * HW + p0 + px) * C3 + lane * 8;
        float4 x0 = *(const float4*)(X + base);
        float4 x1 = *(const float4*)(X + base + 4);
        float4 y0 = *(const float4*)(Y + base);
        float4 y1 = *(const float4*)(Y + base + 4);
        float vv[8] = {x0.x + y0.x, x0.y + y0.y, x0.z + y0.z, x0.w + y0.w,
                       x1.x + y1.x, x1.y + y1.y, x1.z + y1.z, x1.w + y1.w};
        float s = 0.f, ss = 0.f;
#pragma unroll
        for (int u = 0; u < 8; u++) { s += vv[u]; ss += vv[u] * vv[u]; }
#pragma unroll
        for (int o = 16; o; o >>= 1) {
            s  += __shfl_xor_sync(0xffffffffu, s,  o);
            ss += __shfl_xor_sync(0xffffffffu, ss, o);
        }
        float mu = s * (1.f / C3);
        float r  = rsqrtf(ss * (1.f / C3) - mu * mu + 1e-5f);
#pragma unroll
        for (int u = 0; u < 8; u++) {
            int c = lane * 8 + u;
            sm[px][c] = (vv[u] - mu) * r * g[c] + bta[c];
        }
    }
    __syncthreads();
    int px = t & 31, c0 = t >> 5;
    for (int c = c0; c < C3; c += 8)
        out[((long)b * C3 + c) * HW + p0 + px] = sm[px][c];
}

// ---------------- launch ----------------
extern "C" void kernel_launch(void* const* d_in, const int* in_sizes, int n_in,
                              void* d_out, int out_size)
{
    const float* F_lidar = (const float*)d_in[0];
    const float* F_cam   = (const float*)d_in[1];
    const float* Wq  = (const float*)d_in[2];
    const float* Wk  = (const float*)d_in[3];
    const float* Wv  = (const float*)d_in[4];
    const float* Wo  = (const float*)d_in[5];
    const float* Wr  = (const float*)d_in[6];
    const float* g1  = (const float*)d_in[7];
    const float* b1  = (const float*)d_in[8];
    const float* g2  = (const float*)d_in[9];
    const float* b2  = (const float*)d_in[10];
    const float* W1  = (const float*)d_in[11];
    const float* bf1 = (const float*)d_in[12];
    const float* W2  = (const float*)d_in[13];
    const float* bf2 = (const float*)d_in[14];
    float* out = (float*)d_out;

    float *Q, *AO, *X, *Y, *Hd;
    __nv_bfloat162 *K2, *V2;
    cudaGetSymbolAddress((void**)&Q,  g_Q);
    cudaGetSymbolAddress((void**)&K2, g_K2);
    cudaGetSymbolAddress((void**)&V2, g_V2);
    cudaGetSymbolAddress((void**)&AO, g_AO);
    cudaGetSymbolAddress((void**)&X,  g_X);
    cudaGetSymbolAddress((void**)&Y,  g_Y);
    cudaGetSymbolAddress((void**)&Hd, g_Hid);

    dim3 blk(256);
    const long chw  = (long)C3 * HW;      // NCHW batch stride / bf16 elements
    const long c1hw = (long)C1 * HW;
    const long xstr = (long)HW * C3;      // NHWC batch stride

    // raise dynamic smem limit for all used instantiations
    cudaFuncSetAttribute(gemm_tc<0,0,0,0,0,0>, cudaFuncAttributeMaxDynamicSharedMemorySize, GSMEM);
    cudaFuncSetAttribute(gemm_tc<0,0,0,0,0,1>, cudaFuncAttributeMaxDynamicSharedMemorySize, GSMEM);
    cudaFuncSetAttribute(gemm_tc<0,1,0,0,0,0>, cudaFuncAttributeMaxDynamicSharedMemorySize, GSMEM);
    cudaFuncSetAttribute(gemm_tc<1,1,1,0,0,0>, cudaFuncAttributeMaxDynamicSharedMemorySize, GSMEM);
    cudaFuncSetAttribute(gemm_tc<0,0,0,1,1,0>, cudaFuncAttributeMaxDynamicSharedMemorySize, GSMEM);
    cudaFuncSetAttribute(gemm_tc<0,0,0,0,1,0>, cudaFuncAttributeMaxDynamicSharedMemorySize, GSMEM);

    // projections (Q: NCHW fp32; K/V: packed bf16 [cpair][HW])
    gemm_tc<0,0,0,0,0,0><<<dim3(313, 1, BSZ), blk, GSMEM>>>(
        Wq, F_lidar, nullptr, Q, C3, HW, C1, 0, c1hw, chw);
    gemm_tc<0,0,0,0,0,1><<<dim3(313, 1, BSZ), blk, GSMEM>>>(
        Wk, F_cam, nullptr, (float*)K2, C3, HW, C3, 0, chw, chw);
    gemm_tc<0,0,0,0,0,1><<<dim3(313, 1, BSZ), blk, GSMEM>>>(
        Wv, F_cam, nullptr, (float*)V2, C3, HW, C3, 0, chw, chw);

    // attention (NHWC out), two-phase + f32x2
    attn_kernel<<<dim3((HW + 127) / 128, NHEADS, BSZ), dim3(128)>>>(Q, K2, V2, AO);

    // X = AO @ Wo^T ; X += F_lidar^T @ Wr^T
    gemm_tc<0,1,0,0,0,0><<<dim3(2, 313, 1), blk, GSMEM>>>(
        AO, Wo, nullptr, X, BSZ * HW, C3, C3, 0, 0, 0);
    gemm_tc<1,1,1,0,0,0><<<dim3(2, 157, BSZ), blk, GSMEM>>>(
        F_lidar, Wr, nullptr, X, HW, C3, C1, c1hw, 0, xstr);

    // LN1 in place
    ln_kernel<<<(BSZ * HW * 32 + 255) / 256, blk>>>(X, g1, b1, BSZ * HW);

    // FFN
    gemm_tc<0,0,0,1,1,0><<<dim3(8, 313, 1), blk, GSMEM>>>(
        X,  W1, bf1, Hd, BSZ * HW, CF, C3, 0, 0, 0);
    gemm_tc<0,0,0,0,1,0><<<dim3(2, 313, 1), blk, GSMEM>>>(
        Hd, W2, bf2, Y,  BSZ * HW, C3, CF, 0, 0, 0);

    // LN2(x+y) -> NCHW
    final_kernel<<<dim3(HW / 32, BSZ), blk>>>(X, Y, g2, b2, out);
}

// round 13
// speedup vs baseline: 1.0291x; 1.0291x over previous
#include <cuda_runtime.h>
#include <cuda_bf16.h>
#include <math.h>
#include <stdint.h>

#define H_IMG 200
#define W_IMG 200
#define HW    40000
#define C1    64
#define C3    256
#define NHEADS 8
#define HD    32
#define BSZ   2
#define CF    1024
#define ATT_SCALE 0.17677669529663687f   // 32^-0.5

// ---------------- static scratch ----------------
__device__ float           g_Q [BSZ * C3 * HW];          // NCHW fp32
__device__ __nv_bfloat162  g_K2[BSZ * (C3 / 2) * HW];    // [cpair][HW] packed bf16
__device__ __nv_bfloat162  g_V2[BSZ * (C3 / 2) * HW];
__device__ float g_AO [BSZ * HW * C3];   // NHWC
__device__ float g_X  [BSZ * HW * C3];   // NHWC
__device__ float g_Y  [BSZ * HW * C3];   // NHWC
__device__ float g_Hid[BSZ * HW * CF];

__device__ __forceinline__ float f2tf(float x) {
    uint32_t u;
    asm("cvt.rna.tf32.f32 %0, %1;" : "=r"(u) : "f"(x));
    return __uint_as_float(u);
}

// ---------------- f32x2 packed-math helpers ----------------
__device__ __forceinline__ uint64_t pk2(float lo, float hi) {
    uint64_t r;
    asm("mov.b64 %0, {%1, %2};" : "=l"(r) : "f"(lo), "f"(hi));
    return r;
}
__device__ __forceinline__ void upk2(uint64_t v, float& lo, float& hi) {
    asm("mov.b64 {%0, %1}, %2;" : "=f"(lo), "=f"(hi) : "l"(v));
}
__device__ __forceinline__ uint64_t fma2(uint64_t a, uint64_t b, uint64_t c) {
    uint64_t d;
    asm("fma.rn.f32x2 %0, %1, %2, %3;" : "=l"(d) : "l"(a), "l"(b), "l"(c));
    return d;
}
__device__ __forceinline__ uint64_t bf2_to_f2(uint32_t kv) {
    return pk2(__uint_as_float(kv << 16), __uint_as_float(kv & 0xFFFF0000u));
}

// ---------------- GEMM smem layout ----------------
// A and B both k-interleaved: elem (k, r) at [ (k%4)*PL + 4*r + k/4 ].
// One LDS.128 at (tg, r) gives k = {tg, tg+4, tg+8, tg+12}: frags for both kk steps.
#define APL 520              // 4*128 + 8
#define BPL 520
#define ABUF (4 * APL)       // 2080 floats
#define BBUF (4 * BPL)       // 2080 floats
#define SBUF (ABUF + BBUF)   // per-stage floats (4160) -> 2 stages = 33280 B static

// ---------------- tf32 TC GEMM: BM=BN=128, BK=16, 4 warps of 64x64, 128 thr ----
// TA=0: A row-major [M,K] (M multiple of 128 for all TA=0 uses).
// TA=1: A stored [K,M] (row stride M), M-guarded.
// TB=0: B row-major [K,N]. TB=1: B stored [N,K] (B^T used). N-guarded.
// PACKBF: C written as packed bf16 pairs [(m/2)][n], cStr in bf16 elements.
template<int TA, int TB, int ACCU, int RELU, int BIAS, int PACKBF>
__global__ __launch_bounds__(128) void gemm_tc(
    const float* __restrict__ A, const float* __restrict__ B,
    const float* __restrict__ bias, float* __restrict__ C,
    int M, int N, int K, long aStr, long bStr, long cStr)
{
    __shared__ float sm[2 * SBUF];
    A += (long)blockIdx.z * aStr;
    B += (long)blockIdx.z * bStr;
    __nv_bfloat16* cb = (__nv_bfloat16*)C + (long)blockIdx.z * cStr;  // PACKBF path
    if (!PACKBF) C += (long)blockIdx.z * cStr;

    const int m0 = blockIdx.y * 128;
    const int n0 = blockIdx.x * 128;
    const int t    = threadIdx.x;                 // 0..127
    const int lane = t & 31, w = t >> 5;          // 4 warps
    const int g  = lane >> 2, tg = lane & 3;
    const int wm = (w & 1) * 64, wn = (w >> 1) * 64;

    float acc[4][8][4];
#pragma unroll
    for (int i = 0; i < 4; i++)
#pragma unroll
        for (int j = 0; j < 8; j++)
#pragma unroll
            for (int r = 0; r < 4; r++) acc[i][j][r] = 0.f;

    float ra[4][4], rb[4][4];

    auto loadA = [&](int k0) {
#pragma unroll
        for (int v = 0; v < 4; v++) {
            int f = t + v * 128;
            if (TA == 0) {
                int m = f >> 2, kc = (f & 3) << 2;
                float4 q = *(const float4*)(A + (long)(m0 + m) * K + k0 + kc);
                ra[v][0] = q.x; ra[v][1] = q.y; ra[v][2] = q.z; ra[v][3] = q.w;
            } else {
                int k4 = f >> 7, m = f & 127;
                bool ok = (m0 + m) < M;
                const float* p = A + (long)(k0 + 4 * k4) * M + (ok ? m0 + m : 0);
#pragma unroll
                for (int i = 0; i < 4; i++)
                    ra[v][i] = ok ? p[(long)i * M] : 0.f;
            }
        }
    };
    auto loadB = [&](int k0) {
        int k4 = t & 3;
#pragma unroll
        for (int v = 0; v < 4; v++) {
            int n = (t >> 2) + 32 * v;
            bool ok = (n0 + n) < N;
            if (TB == 0) {
                const float* p = B + (long)(k0 + 4 * k4) * N + (ok ? n0 + n : 0);
#pragma unroll
                for (int i = 0; i < 4; i++)
                    rb[v][i] = ok ? p[(long)i * N] : 0.f;
            } else {
                float4 q = make_float4(0.f, 0.f, 0.f, 0.f);
                if (ok) q = *(const float4*)(B + (long)(n0 + n) * K + k0 + 4 * k4);
                rb[v][0] = q.x; rb[v][1] = q.y; rb[v][2] = q.z; rb[v][3] = q.w;
            }
        }
    };
    auto storeAB = [&](int s) {
        float* As = sm + s * SBUF;
        float* Bs = As + ABUF;
#pragma unroll
        for (int v = 0; v < 4; v++) {
            int f = t + v * 128;
            if (TA == 0) {
                int m = f >> 2, j = f & 3;
#pragma unroll
                for (int i = 0; i < 4; i++)          // k = 4j + i -> plane i, idx j
                    As[APL * i + 4 * m + j] = f2tf(ra[v][i]);
            } else {
                int k4 = f >> 7, m = f & 127;
#pragma unroll
                for (int i = 0; i < 4; i++)          // k = 4k4 + i
                    As[APL * i + 4 * m + k4] = f2tf(ra[v][i]);
            }
        }
        {
            int k4 = t & 3;
#pragma unroll
            for (int v = 0; v < 4; v++) {
                int n = (t >> 2) + 32 * v;
#pragma unroll
                for (int i = 0; i < 4; i++)          // k = 4k4 + i
                    Bs[BPL * i + 4 * n + k4] = f2tf(rb[v][i]);
            }
        }
    };
    auto compute = [&](int s) {
        const float* As = sm + s * SBUF;
        const float* Bs = As + ABUF;
        float4 bq[8];
#pragma unroll
        for (int ns = 0; ns < 8; ns++)
            bq[ns] = *(const float4*)&Bs[BPL * tg + 4 * (wn + 8 * ns + g)];
#pragma unroll
        for (int ms = 0; ms < 4; ms++) {
            int m = wm + 16 * ms + g;
            float4 alo = *(const float4*)&As[APL * tg + 4 * m];
            float4 ahi = *(const float4*)&As[APL * tg + 4 * (m + 8)];
#pragma unroll
            for (int ns = 0; ns < 8; ns++) {
                asm volatile(
                    "mma.sync.aligned.m16n8k8.row.col.f32.tf32.tf32.f32 "
                    "{%0,%1,%2,%3}, {%4,%5,%6,%7}, {%8,%9}, {%0,%1,%2,%3};\n"
                    : "+f"(acc[ms][ns][0]), "+f"(acc[ms][ns][1]),
                      "+f"(acc[ms][ns][2]), "+f"(acc[ms][ns][3])
                    : "r"(__float_as_uint(alo.x)), "r"(__float_as_uint(ahi.x)),
                      "r"(__float_as_uint(alo.y)), "r"(__float_as_uint(ahi.y)),
                      "r"(__float_as_uint(bq[ns].x)), "r"(__float_as_uint(bq[ns].y)));
                asm volatile(
                    "mma.sync.aligned.m16n8k8.row.col.f32.tf32.tf32.f32 "
                    "{%0,%1,%2,%3}, {%4,%5,%6,%7}, {%8,%9}, {%0,%1,%2,%3};\n"
                    : "+f"(acc[ms][ns][0]), "+f"(acc[ms][ns][1]),
                      "+f"(acc[ms][ns][2]), "+f"(acc[ms][ns][3])
                    : "r"(__float_as_uint(alo.z)), "r"(__float_as_uint(ahi.z)),
                      "r"(__float_as_uint(alo.w)), "r"(__float_as_uint(ahi.w)),
                      "r"(__float_as_uint(bq[ns].z)), "r"(__float_as_uint(bq[ns].w)));
            }
        }
    };

    const int ktiles = K >> 4;
    loadA(0); loadB(0);
    storeAB(0);
    __syncthreads();
    for (int kt = 0; kt < ktiles; kt++) {
        int buf = kt & 1;
        if (kt + 1 < ktiles) { loadA((kt + 1) << 4); loadB((kt + 1) << 4); }
        compute(buf);
        if (kt + 1 < ktiles) storeAB(buf ^ 1);
        __syncthreads();
    }

    // epilogue
#pragma unroll
    for (int ms = 0; ms < 4; ms++) {
#pragma unroll
        for (int ns = 0; ns < 8; ns++) {
            int ncol = n0 + wn + ns * 8 + tg * 2;
            if (ncol >= N) continue;
            int mrow = m0 + wm + ms * 16 + g;
#pragma unroll
            for (int r = 0; r < 2; r++) {
                int m = mrow + r * 8;
                if (m >= M) continue;
                float v0 = acc[ms][ns][r * 2];
                float v1 = acc[ms][ns][r * 2 + 1];
                if (PACKBF) {
                    long base = ((long)(m >> 1) * N + ncol) * 2 + (m & 1);
                    cb[base]     = __float2bfloat16(v0);
                    cb[base + 2] = __float2bfloat16(v1);
                } else {
                    if (BIAS) { v0 += bias[ncol]; v1 += bias[ncol + 1]; }
                    if (RELU) { v0 = fmaxf(v0, 0.f); v1 = fmaxf(v1, 0.f); }
                    float2* p = (float2*)(C + (long)m * N + ncol);
                    if (ACCU) { float2 o = *p; v0 += o.x; v1 += o.y; }
                    *p = make_float2(v0, v1);
                }
            }
        }
    }
}

// ---------------- 7x7 local-window attention, two-phase + f32x2 ----------------
__global__ __launch_bounds__(128) void attn_kernel(
    const float* __restrict__ Q, const __nv_bfloat162* __restrict__ K,
    const __nv_bfloat162* __restrict__ V, float* __restrict__ O)
{
    __shared__ float sc[128][49];
    const int b = blockIdx.z, nh = blockIdx.y;
    const int t = threadIdx.x;
    const int hw = blockIdx.x * 128 + t;
    if (hw >= HW) return;
    const int h = hw / W_IMG, w = hw % W_IMG;

    const int cbase = (b * C3 + nh * HD) * HW;
    const long kvbase = ((long)b * (C3 / 2) + nh * (HD / 2)) * HW;
    const uint32_t* kb = (const uint32_t*)(K + kvbase);
    const uint32_t* vb = (const uint32_t*)(V + kvbase);

    uint64_t q2[HD / 2];
#pragma unroll
    for (int dp = 0; dp < HD / 2; dp++)
        q2[dp] = pk2(Q[cbase + (2 * dp) * HW + hw], Q[cbase + (2 * dp + 1) * HW + hw]);

    float mx = -1e30f;
    {
        int o = 0;
        for (int i = 0; i < 7; i++) {
            int hh = min(max(h + i - 3, 0), H_IMG - 1);
            int rbase = hh * W_IMG;
#pragma unroll
            for (int j = 0; j < 7; j++) {
                int ww = min(max(w + j - 3, 0), W_IMG - 1);
                int off = rbase + ww;
                uint64_t s2 = pk2(0.f, 0.f);
#pragma unroll
                for (int dp = 0; dp < HD / 2; dp++)
                    s2 = fma2(q2[dp], bf2_to_f2(kb[dp * HW + off]), s2);
                float a, c;
                upk2(s2, a, c);
                float s = (a + c) * ATT_SCALE;
                mx = fmaxf(mx, s);
                sc[t][o++] = s;
            }
        }
    }

    float l = 0.f;
    uint64_t acc2[HD / 2];
#pragma unroll
    for (int dp = 0; dp < HD / 2; dp++) acc2[dp] = pk2(0.f, 0.f);
    {
        int o = 0;
        for (int i = 0; i < 7; i++) {
            int hh = min(max(h + i - 3, 0), H_IMG - 1);
            int rbase = hh * W_IMG;
#pragma unroll
            for (int j = 0; j < 7; j++) {
                int ww = min(max(w + j - 3, 0), W_IMG - 1);
                int off = rbase + ww;
                float p = __expf(sc[t][o++] - mx);
                l += p;
                uint64_t p2 = pk2(p, p);
#pragma unroll
                for (int dp = 0; dp < HD / 2; dp++)
                    acc2[dp] = fma2(bf2_to_f2(vb[dp * HW + off]), p2, acc2[dp]);
            }
        }
    }
    float inv = 1.f / l;
    float* ob = O + ((long)(b * HW + hw)) * C3 + nh * HD;   // NHWC
#pragma unroll
    for (int dp = 0; dp < HD / 2; dp += 2) {
        float a0, a1, a2, a3;
        upk2(acc2[dp], a0, a1);
        upk2(acc2[dp + 1], a2, a3);
        *(float4*)(ob + 2 * dp) = make_float4(a0 * inv, a1 * inv, a2 * inv, a3 * inv);
    }
}

// ---------------- warp-per-pixel LayerNorm (in place, NHWC) --------
__global__ __launch_bounds__(256) void ln_kernel(
    float* __restrict__ X, const float* __restrict__ g, const float* __restrict__ bta,
    int npix)
{
    int wrp  = (blockIdx.x * blockDim.x + threadIdx.x) >> 5;
    int lane = threadIdx.x & 31;
    if (wrp >= npix) return;
    float* xp = X + (long)wrp * C3 + lane * 8;
    float4 v0 = *(float4*)xp;
    float4 v1 = *(float4*)(xp + 4);
    float s  = v0.x + v0.y + v0.z + v0.w + v1.x + v1.y + v1.z + v1.w;
    float ss = v0.x*v0.x + v0.y*v0.y + v0.z*v0.z + v0.w*v0.w
             + v1.x*v1.x + v1.y*v1.y + v1.z*v1.z + v1.w*v1.w;
#pragma unroll
    for (int o = 16; o; o >>= 1) {
        s  += __shfl_xor_sync(0xffffffffu, s,  o);
        ss += __shfl_xor_sync(0xffffffffu, ss, o);
    }
    float mu = s * (1.f / C3);
    float r  = rsqrtf(ss * (1.f / C3) - mu * mu + 1e-5f);
    const float* gp = g   + lane * 8;
    const float* bp = bta + lane * 8;
    float vv[8] = {v0.x, v0.y, v0.z, v0.w, v1.x, v1.y, v1.z, v1.w};
#pragma unroll
    for (int u = 0; u < 8; u++) vv[u] = (vv[u] - mu) * r * gp[u] + bp[u];
    *(float4*)xp       = make_float4(vv[0], vv[1], vv[2], vv[3]);
    *(float4*)(xp + 4) = make_float4(vv[4], vv[5], vv[6], vv[7]);
}

// ---------------- x = LN2(x + y), NHWC -> NCHW output ----------------
__global__ __launch_bounds__(256) void final_kernel(
    const float* __restrict__ X, const float* __restrict__ Y,
    const float* __restrict__ g, const float* __restrict__ bta,
    float* __restrict__ out)
{
    __shared__ float sm[32][264];
    const int b  = blockIdx.y;
    const int p0 = blockIdx.x * 32;
    const int t = threadIdx.x, lane = t & 31, wid = t >> 5;

    for (int qq = 0; qq < 4; qq++) {
        int px = wid * 4 + qq;
        long base = ((long)b * HW + p0 + px) * C3 + lane * 8;
        float4 x0 = *(const float4*)(X + base);
        float4 x1 = *(const float4*)(X + base + 4);
        float4 y0 = *(const float4*)(Y + base);
        float4 y1 = *(const float4*)(Y + base + 4);
        float vv[8] = {x0.x + y0.x, x0.y + y0.y, x0.z + y0.z, x0.w + y0.w,
                       x1.x + y1.x, x1.y + y1.y, x1.z + y1.z, x1.w + y1.w};
        float s = 0.f, ss = 0.f;
#pragma unroll
        for (int u = 0; u < 8; u++) { s += vv[u]; ss += vv[u] * vv[u]; }
#pragma unroll
        for (int o = 16; o; o >>= 1) {
            s  += __shfl_xor_sync(0xffffffffu, s,  o);
            ss += __shfl_xor_sync(0xffffffffu, ss, o);
        }
        float mu = s * (1.f / C3);
        float r  = rsqrtf(ss * (1.f / C3) - mu * mu + 1e-5f);
#pragma unroll
        for (int u = 0; u < 8; u++) {
            int c = lane * 8 + u;
            sm[px][c] = (vv[u] - mu) * r * g[c] + bta[c];
        }
    }
    __syncthreads();
    int px = t & 31, c0 = t >> 5;
    for (int c = c0; c < C3; c += 8)
        out[((long)b * C3 + c) * HW + p0 + px] = sm[px][c];
}

// ---------------- launch ----------------
extern "C" void kernel_launch(void* const* d_in, const int* in_sizes, int n_in,
                              void* d_out, int out_size)
{
    const float* F_lidar = (const float*)d_in[0];
    const float* F_cam   = (const float*)d_in[1];
    const float* Wq  = (const float*)d_in[2];
    const float* Wk  = (const float*)d_in[3];
    const float* Wv  = (const float*)d_in[4];
    const float* Wo  = (const float*)d_in[5];
    const float* Wr  = (const float*)d_in[6];
    const float* g1  = (const float*)d_in[7];
    const float* b1  = (const float*)d_in[8];
    const float* g2  = (const float*)d_in[9];
    const float* b2  = (const float*)d_in[10];
    const float* W1  = (const float*)d_in[11];
    const float* bf1 = (const float*)d_in[12];
    const float* W2  = (const float*)d_in[13];
    const float* bf2 = (const float*)d_in[14];
    float* out = (float*)d_out;

    float *Q, *AO, *X, *Y, *Hd;
    __nv_bfloat162 *K2, *V2;
    cudaGetSymbolAddress((void**)&Q,  g_Q);
    cudaGetSymbolAddress((void**)&K2, g_K2);
    cudaGetSymbolAddress((void**)&V2, g_V2);
    cudaGetSymbolAddress((void**)&AO, g_AO);
    cudaGetSymbolAddress((void**)&X,  g_X);
    cudaGetSymbolAddress((void**)&Y,  g_Y);
    cudaGetSymbolAddress((void**)&Hd, g_Hid);

    dim3 gblk(128);
    dim3 blk(256);
    const long chw  = (long)C3 * HW;      // NCHW batch stride / bf16 elements
    const long c1hw = (long)C1 * HW;
    const long xstr = (long)HW * C3;      // NHWC batch stride

    // projections (Q: NCHW fp32; K/V: packed bf16 [cpair][HW])
    gemm_tc<0,0,0,0,0,0><<<dim3(313, 2, BSZ), gblk>>>(
        Wq, F_lidar, nullptr, Q, C3, HW, C1, 0, c1hw, chw);
    gemm_tc<0,0,0,0,0,1><<<dim3(313, 2, BSZ), gblk>>>(
        Wk, F_cam, nullptr, (float*)K2, C3, HW, C3, 0, chw, chw);
    gemm_tc<0,0,0,0,0,1><<<dim3(313, 2, BSZ), gblk>>>(
        Wv, F_cam, nullptr, (float*)V2, C3, HW, C3, 0, chw, chw);

    // attention (NHWC out), two-phase + f32x2
    attn_kernel<<<dim3((HW + 127) / 128, NHEADS, BSZ), dim3(128)>>>(Q, K2, V2, AO);

    // X = AO @ Wo^T ; X += F_lidar^T @ Wr^T
    gemm_tc<0,1,0,0,0,0><<<dim3(2, 625, 1), gblk>>>(
        AO, Wo, nullptr, X, BSZ * HW, C3, C3, 0, 0, 0);
    gemm_tc<1,1,1,0,0,0><<<dim3(2, 313, BSZ), gblk>>>(
        F_lidar, Wr, nullptr, X, HW, C3, C1, c1hw, 0, xstr);

    // LN1 in place
    ln_kernel<<<(BSZ * HW * 32 + 255) / 256, blk>>>(X, g1, b1, BSZ * HW);

    // FFN
    gemm_tc<0,0,0,1,1,0><<<dim3(8, 625, 1), gblk>>>(
        X,  W1, bf1, Hd, BSZ * HW, CF, C3, 0, 0, 0);
    gemm_tc<0,0,0,0,1,0><<<dim3(2, 625, 1), gblk>>>(
        Hd, W2, bf2, Y,  BSZ * HW, C3, CF, 0, 0, 0);

    // LN2(x+y) -> NCHW
    final_kernel<<<dim3(HW / 32, BSZ), blk>>>(X, Y, g2, b2, out);
}

// round 14
// speedup vs baseline: 1.4028x; 1.3631x over previous
#include <cuda_runtime.h>
#include <cuda_bf16.h>
#include <math.h>
#include <stdint.h>

#define H_IMG 200
#define W_IMG 200
#define HW    40000
#define C1    64
#define C3    256
#define NHEADS 8
#define HD    32
#define BSZ   2
#define CF    1024
#define ATT_SCALE 0.17677669529663687f   // 32^-0.5

// ---------------- static scratch ----------------
__device__ float           g_Q [BSZ * C3 * HW];          // NCHW fp32
__device__ __nv_bfloat162  g_K2[BSZ * (C3 / 2) * HW];    // [cpair][HW] packed bf16
__device__ __nv_bfloat162  g_V2[BSZ * (C3 / 2) * HW];
__device__ float g_AO [BSZ * HW * C3];   // NHWC
__device__ float g_X  [BSZ * HW * C3];   // NHWC
__device__ float g_Y  [BSZ * HW * C3];   // NHWC
__device__ float g_Hid[BSZ * HW * CF];

__device__ __forceinline__ float f2tf(float x) {
    uint32_t u;
    asm("cvt.rna.tf32.f32 %0, %1;" : "=r"(u) : "f"(x));
    return __uint_as_float(u);
}

// ---------------- f32x2 packed-math helpers ----------------
__device__ __forceinline__ uint64_t pk2(float lo, float hi) {
    uint64_t r;
    asm("mov.b64 %0, {%1, %2};" : "=l"(r) : "f"(lo), "f"(hi));
    return r;
}
__device__ __forceinline__ void upk2(uint64_t v, float& lo, float& hi) {
    asm("mov.b64 {%0, %1}, %2;" : "=f"(lo), "=f"(hi) : "l"(v));
}
__device__ __forceinline__ uint64_t fma2(uint64_t a, uint64_t b, uint64_t c) {
    uint64_t d;
    asm("fma.rn.f32x2 %0, %1, %2, %3;" : "=l"(d) : "l"(a), "l"(b), "l"(c));
    return d;
}
__device__ __forceinline__ uint64_t bf2_to_f2(uint32_t kv) {
    return pk2(__uint_as_float(kv << 16), __uint_as_float(kv & 0xFFFF0000u));
}

// ---------------- GEMM smem layout (R9 champion config) ----------------
// A k-interleaved: elem (k, m) at [ (k%4)*ATG + 4*m + k/4 ].
// One LDS.128 at (tg, m) -> k = {tg, tg+4, tg+8, tg+12}: A-frags for both kk steps.
// B flat [k][136 + n].
#define ATG 520
#define ABUF 2080            // 4 * 520
#define BBUF 2176            // 16 * 136
#define SBUF (ABUF + BBUF)   // per stage

// ---------------- tf32 TC GEMM: BM=BN=128, BK=16, 8 warps of 64x32, 256 thr ----
// TA=0: A row-major [M,K] (M multiple of 128).
// TA=1: A stored [K,M] (row stride M), M-guarded.
// TA=2: CONCAT mode: k < C3 from A (row-major [M,C3], M-guarded);
//       k >= C3 from A2 (stored [K2,M], row stride M, M-guarded);
//       B from Bm [N,C3] for k < C3 else B2m [N,K-C3]. (TB ignored.)
// TB=0: B row-major [K,N]. TB=1: B stored [N,K] (B^T used). N-guarded.
// PACKBF: C written as packed bf16 pairs [(m/2)][n], cStr in bf16 elements.
template<int TA, int TB, int ACCU, int RELU, int BIAS, int PACKBF>
__global__ __launch_bounds__(256) void gemm_tc(
    const float* __restrict__ A, const float* __restrict__ B,
    const float* __restrict__ A2, const float* __restrict__ B2,
    const float* __restrict__ bias, float* __restrict__ C,
    int M, int N, int K, long aStr, long a2Str, long bStr, long cStr)
{
    __shared__ float sm[2 * SBUF];
    A += (long)blockIdx.z * aStr;
    B += (long)blockIdx.z * bStr;
    if (TA == 2) A2 += (long)blockIdx.z * a2Str;
    __nv_bfloat16* cb = (__nv_bfloat16*)C + (long)blockIdx.z * cStr;  // PACKBF path
    if (!PACKBF) C += (long)blockIdx.z * cStr;

    const int m0 = blockIdx.y * 128;
    const int n0 = blockIdx.x * 128;
    const int t    = threadIdx.x;
    const int lane = t & 31, w = t >> 5;
    const int g  = lane >> 2, tg = lane & 3;
    const int wmB = (w & 1) * 64, wnB = (w >> 1) * 32;

    float acc[4][4][4];
#pragma unroll
    for (int i = 0; i < 4; i++)
#pragma unroll
        for (int j = 0; j < 4; j++)
#pragma unroll
            for (int r = 0; r < 4; r++) acc[i][j][r] = 0.f;

    float ra[2][4], rb[2][4];

    auto loadA = [&](int k0) {
#pragma unroll
        for (int v = 0; v < 2; v++) {
            int f = t + v * 256;
            if (TA == 0) {
                int m = f >> 2, kc = (f & 3) << 2;
                float4 q = *(const float4*)(A + (long)(m0 + m) * K + k0 + kc);
                ra[v][0] = q.x; ra[v][1] = q.y; ra[v][2] = q.z; ra[v][3] = q.w;
            } else if (TA == 1) {
                int k4 = f >> 7, m = f & 127;
                bool ok = (m0 + m) < M;
                const float* p = A + (long)(k0 + 4 * k4) * M + (ok ? m0 + m : 0);
#pragma unroll
                for (int i = 0; i < 4; i++)
                    ra[v][i] = ok ? p[(long)i * M] : 0.f;
            } else {  // TA == 2, concat
                if (k0 < C3) {
                    int m = f >> 2, kc = (f & 3) << 2;
                    bool ok = (m0 + m) < M;
                    float4 q = make_float4(0.f, 0.f, 0.f, 0.f);
                    if (ok) q = *(const float4*)(A + (long)(m0 + m) * C3 + k0 + kc);
                    ra[v][0] = q.x; ra[v][1] = q.y; ra[v][2] = q.z; ra[v][3] = q.w;
                } else {
                    int k4 = f >> 7, m = f & 127;
                    bool ok = (m0 + m) < M;
                    const float* p = A2 + (long)(k0 - C3 + 4 * k4) * M + (ok ? m0 + m : 0);
#pragma unroll
                    for (int i = 0; i < 4; i++)
                        ra[v][i] = ok ? p[(long)i * M] : 0.f;
                }
            }
        }
    };
    auto loadB = [&](int k0) {
#pragma unroll
        for (int v = 0; v < 2; v++) {
            int f = t + v * 256;
            if (TA == 2) {
                // B^T concat: n rows; k < C3 from B [N, C3], else B2 [N, K-C3]
                int n = f >> 2, kc = (f & 3) << 2;
                float4 q;
                if (k0 < C3)
                    q = *(const float4*)(B  + (long)(n0 + n) * C3 + k0 + kc);
                else
                    q = *(const float4*)(B2 + (long)(n0 + n) * (K - C3) + (k0 - C3) + kc);
                rb[v][0] = q.x; rb[v][1] = q.y; rb[v][2] = q.z; rb[v][3] = q.w;
            } else if (TB == 0) {
                int k = f >> 5, n = (f & 31) << 2;
                float4 q = make_float4(0.f, 0.f, 0.f, 0.f);
                if (n0 + n < N)
                    q = *(const float4*)(B + (long)(k0 + k) * N + n0 + n);
                rb[v][0] = q.x; rb[v][1] = q.y; rb[v][2] = q.z; rb[v][3] = q.w;
            } else {
                int n = f >> 2, kc = (f & 3) << 2;
                float4 q = make_float4(0.f, 0.f, 0.f, 0.f);
                if (n0 + n < N)
                    q = *(const float4*)(B + (long)(n0 + n) * K + k0 + kc);
                rb[v][0] = q.x; rb[v][1] = q.y; rb[v][2] = q.z; rb[v][3] = q.w;
            }
        }
    };
    auto storeAB = [&](int s, int k0) {
        float* As = sm + s * SBUF;
        float* Bs = As + ABUF;
#pragma unroll
        for (int v = 0; v < 2; v++) {
            int f = t + v * 256;
            // A store
            if (TA == 0 || (TA == 2 && k0 < C3)) {
                int m = f >> 2, j = f & 3;
#pragma unroll
                for (int i = 0; i < 4; i++)
                    As[ATG * i + 4 * m + j] = f2tf(ra[v][i]);
            } else {
                int k4 = f >> 7, m = f & 127;
#pragma unroll
                for (int i = 0; i < 4; i++)
                    As[ATG * i + 4 * m + k4] = f2tf(ra[v][i]);
            }
            // B store
            if (TA == 2 || TB == 1) {
                int n = f >> 2, kc = (f & 3) << 2;
#pragma unroll
                for (int i = 0; i < 4; i++)
                    Bs[(kc + i) * 136 + n] = f2tf(rb[v][i]);
            } else {
                int k = f >> 5, n = (f & 31) << 2;
                float4 q = make_float4(f2tf(rb[v][0]), f2tf(rb[v][1]),
                                       f2tf(rb[v][2]), f2tf(rb[v][3]));
                *(float4*)&Bs[k * 136 + n] = q;
            }
        }
    };
    auto compute = [&](int s) {
        const float* As = sm + s * SBUF;
        const float* Bs = As + ABUF;
        uint32_t bfr[2][4][2];
#pragma unroll
        for (int kk2 = 0; kk2 < 2; kk2++) {
            int rA = kk2 * 8 + tg, rB = rA + 4;
#pragma unroll
            for (int ns = 0; ns < 4; ns++) {
                int n = wnB + ns * 8 + g;
                bfr[kk2][ns][0] = __float_as_uint(Bs[rA * 136 + n]);
                bfr[kk2][ns][1] = __float_as_uint(Bs[rB * 136 + n]);
            }
        }
#pragma unroll
        for (int ms = 0; ms < 4; ms++) {
            int m = wmB + ms * 16 + g;
            float4 alo = *(const float4*)&As[ATG * tg + 4 * m];
            float4 ahi = *(const float4*)&As[ATG * tg + 4 * (m + 8)];
#pragma unroll
            for (int ns = 0; ns < 4; ns++) {
                asm volatile(
                    "mma.sync.aligned.m16n8k8.row.col.f32.tf32.tf32.f32 "
                    "{%0,%1,%2,%3}, {%4,%5,%6,%7}, {%8,%9}, {%0,%1,%2,%3};\n"
                    : "+f"(acc[ms][ns][0]), "+f"(acc[ms][ns][1]),
                      "+f"(acc[ms][ns][2]), "+f"(acc[ms][ns][3])
                    : "r"(__float_as_uint(alo.x)), "r"(__float_as_uint(ahi.x)),
                      "r"(__float_as_uint(alo.y)), "r"(__float_as_uint(ahi.y)),
                      "r"(bfr[0][ns][0]), "r"(bfr[0][ns][1]));
                asm volatile(
                    "mma.sync.aligned.m16n8k8.row.col.f32.tf32.tf32.f32 "
                    "{%0,%1,%2,%3}, {%4,%5,%6,%7}, {%8,%9}, {%0,%1,%2,%3};\n"
                    : "+f"(acc[ms][ns][0]), "+f"(acc[ms][ns][1]),
                      "+f"(acc[ms][ns][2]), "+f"(acc[ms][ns][3])
                    : "r"(__float_as_uint(alo.z)), "r"(__float_as_uint(ahi.z)),
                      "r"(__float_as_uint(alo.w)), "r"(__float_as_uint(ahi.w)),
                      "r"(bfr[1][ns][0]), "r"(bfr[1][ns][1]));
            }
        }
    };

    const int ktiles = K >> 4;
    loadA(0); loadB(0);
    storeAB(0, 0);
    __syncthreads();
    for (int kt = 0; kt < ktiles; kt++) {
        int buf = kt & 1;
        if (kt + 1 < ktiles) { loadA((kt + 1) << 4); loadB((kt + 1) << 4); }
        compute(buf);
        if (kt + 1 < ktiles) storeAB(buf ^ 1, (kt + 1) << 4);
        __syncthreads();
    }

    // epilogue
#pragma unroll
    for (int ms = 0; ms < 4; ms++) {
#pragma unroll
        for (int ns = 0; ns < 4; ns++) {
            int ncol = n0 + wnB + ns * 8 + tg * 2;
            if (ncol >= N) continue;
            int mrow = m0 + wmB + ms * 16 + g;
#pragma unroll
            for (int r = 0; r < 2; r++) {
                int m = mrow + r * 8;
                if (m >= M) continue;
                float v0 = acc[ms][ns][r * 2];
                float v1 = acc[ms][ns][r * 2 + 1];
                if (PACKBF) {
                    long base = ((long)(m >> 1) * N + ncol) * 2 + (m & 1);
                    cb[base]     = __float2bfloat16(v0);
                    cb[base + 2] = __float2bfloat16(v1);
                } else {
                    if (BIAS) { v0 += bias[ncol]; v1 += bias[ncol + 1]; }
                    if (RELU) { v0 = fmaxf(v0, 0.f); v1 = fmaxf(v1, 0.f); }
                    float2* p = (float2*)(C + (long)m * N + ncol);
                    if (ACCU) { float2 o = *p; v0 += o.x; v1 += o.y; }
                    *p = make_float2(v0, v1);
                }
            }
        }
    }
}

// ---------------- 7x7 local-window attention, two-phase + f32x2 ----------------
__global__ __launch_bounds__(128) void attn_kernel(
    const float* __restrict__ Q, const __nv_bfloat162* __restrict__ K,
    const __nv_bfloat162* __restrict__ V, float* __restrict__ O)
{
    __shared__ float sc[128][49];
    const int b = blockIdx.z, nh = blockIdx.y;
    const int t = threadIdx.x;
    const int hw = blockIdx.x * 128 + t;
    if (hw >= HW) return;
    const int h = hw / W_IMG, w = hw % W_IMG;

    const int cbase = (b * C3 + nh * HD) * HW;
    const long kvbase = ((long)b * (C3 / 2) + nh * (HD / 2)) * HW;
    const uint32_t* kb = (const uint32_t*)(K + kvbase);
    const uint32_t* vb = (const uint32_t*)(V + kvbase);

    uint64_t q2[HD / 2];
#pragma unroll
    for (int dp = 0; dp < HD / 2; dp++)
        q2[dp] = pk2(Q[cbase + (2 * dp) * HW + hw], Q[cbase + (2 * dp + 1) * HW + hw]);

    float mx = -1e30f;
    {
        int o = 0;
        for (int i = 0; i < 7; i++) {
            int hh = min(max(h + i - 3, 0), H_IMG - 1);
            int rbase = hh * W_IMG;
#pragma unroll
            for (int j = 0; j < 7; j++) {
                int ww = min(max(w + j - 3, 0), W_IMG - 1);
                int off = rbase + ww;
                uint64_t s2 = pk2(0.f, 0.f);
#pragma unroll
                for (int dp = 0; dp < HD / 2; dp++)
                    s2 = fma2(q2[dp], bf2_to_f2(kb[dp * HW + off]), s2);
                float a, c;
                upk2(s2, a, c);
                float s = (a + c) * ATT_SCALE;
                mx = fmaxf(mx, s);
                sc[t][o++] = s;
            }
        }
    }

    float l = 0.f;
    uint64_t acc2[HD / 2];
#pragma unroll
    for (int dp = 0; dp < HD / 2; dp++) acc2[dp] = pk2(0.f, 0.f);
    {
        int o = 0;
        for (int i = 0; i < 7; i++) {
            int hh = min(max(h + i - 3, 0), H_IMG - 1);
            int rbase = hh * W_IMG;
#pragma unroll
            for (int j = 0; j < 7; j++) {
                int ww = min(max(w + j - 3, 0), W_IMG - 1);
                int off = rbase + ww;
                float p = __expf(sc[t][o++] - mx);
                l += p;
                uint64_t p2 = pk2(p, p);
#pragma unroll
                for (int dp = 0; dp < HD / 2; dp++)
                    acc2[dp] = fma2(bf2_to_f2(vb[dp * HW + off]), p2, acc2[dp]);
            }
        }
    }
    float inv = 1.f / l;
    float* ob = O + ((long)(b * HW + hw)) * C3 + nh * HD;   // NHWC
#pragma unroll
    for (int dp = 0; dp < HD / 2; dp += 2) {
        float a0, a1, a2, a3;
        upk2(acc2[dp], a0, a1);
        upk2(acc2[dp + 1], a2, a3);
        *(float4*)(ob + 2 * dp) = make_float4(a0 * inv, a1 * inv, a2 * inv, a3 * inv);
    }
}

// ---------------- warp-per-pixel LayerNorm (in place, NHWC) --------
__global__ __launch_bounds__(256) void ln_kernel(
    float* __restrict__ X, const float* __restrict__ g, const float* __restrict__ bta,
    int npix)
{
    int wrp  = (blockIdx.x * blockDim.x + threadIdx.x) >> 5;
    int lane = threadIdx.x & 31;
    if (wrp >= npix) return;
    float* xp = X + (long)wrp * C3 + lane * 8;
    float4 v0 = *(float4*)xp;
    float4 v1 = *(float4*)(xp + 4);
    float s  = v0.x + v0.y + v0.z + v0.w + v1.x + v1.y + v1.z + v1.w;
    float ss = v0.x*v0.x + v0.y*v0.y + v0.z*v0.z + v0.w*v0.w
             + v1.x*v1.x + v1.y*v1.y + v1.z*v1.z + v1.w*v1.w;
#pragma unroll
    for (int o = 16; o; o >>= 1) {
        s  += __shfl_xor_sync(0xffffffffu, s,  o);
        ss += __shfl_xor_sync(0xffffffffu, ss, o);
    }
    float mu = s * (1.f / C3);
    float r  = rsqrtf(ss * (1.f / C3) - mu * mu + 1e-5f);
    const float* gp = g   + lane * 8;
    const float* bp = bta + lane * 8;
    float vv[8] = {v0.x, v0.y, v0.z, v0.w, v1.x, v1.y, v1.z, v1.w};
#pragma unroll
    for (int u = 0; u < 8; u++) vv[u] = (vv[u] - mu) * r * gp[u] + bp[u];
    *(float4*)xp       = make_float4(vv[0], vv[1], vv[2], vv[3]);
    *(float4*)(xp + 4) = make_float4(vv[4], vv[5], vv[6], vv[7]);
}

// ---------------- x = LN2(x + y), NHWC -> NCHW output ----------------
__global__ __launch_bounds__(256) void final_kernel(
    const float* __restrict__ X, const float* __restrict__ Y,
    const float* __restrict__ g, const float* __restrict__ bta,
    float* __restrict__ out)
{
    __shared__ float sm[32][264];
    const int b  = blockIdx.y;
    const int p0 = blockIdx.x * 32;
    const int t = threadIdx.x, lane = t & 31, wid = t >> 5;

    for (int qq = 0; qq < 4; qq++) {
        int px = wid * 4 + qq;
        long base = ((long)b * HW + p0 + px) * C3 + lane * 8;
        float4 x0 = *(const float4*)(X + base);
        float4 x1 = *(const float4*)(X + base + 4);
        float4 y0 = *(const float4*)(Y + base);
        float4 y1 = *(const float4*)(Y + base + 4);
        float vv[8] = {x0.x + y0.x, x0.y + y0.y, x0.z + y0.z, x0.w + y0.w,
                       x1.x + y1.x, x1.y + y1.y, x1.z + y1.z, x1.w + y1.w};
        float s = 0.f, ss = 0.f;
#pragma unroll
        for (int u = 0; u < 8; u++) { s += vv[u]; ss += vv[u] * vv[u]; }
#pragma unroll
        for (int o = 16; o; o >>= 1) {
            s  += __shfl_xor_sync(0xffffffffu, s,  o);
            ss += __shfl_xor_sync(0xffffffffu, ss, o);
        }
        float mu = s * (1.f / C3);
        float r  = rsqrtf(ss * (1.f / C3) - mu * mu + 1e-5f);
#pragma unroll
        for (int u = 0; u < 8; u++) {
            int c = lane * 8 + u;
            sm[px][c] = (vv[u] - mu) * r * g[c] + bta[c];
        }
    }
    __syncthreads();
    int px = t & 31, c0 = t >> 5;
    for (int c = c0; c < C3; c += 8)
        out[((long)b * C3 + c) * HW + p0 + px] = sm[px][c];
}

// ---------------- launch ----------------
extern "C" void kernel_launch(void* const* d_in, const int* in_sizes, int n_in,
                              void* d_out, int out_size)
{
    const float* F_lidar = (const float*)d_in[0];
    const float* F_cam   = (const float*)d_in[1];
    const float* Wq  = (const float*)d_in[2];
    const float* Wk  = (const float*)d_in[3];
    const float* Wv  = (const float*)d_in[4];
    const float* Wo  = (const float*)d_in[5];
    const float* Wr  = (const float*)d_in[6];
    const float* g1  = (const float*)d_in[7];
    const float* b1  = (const float*)d_in[8];
    const float* g2  = (const float*)d_in[9];
    const float* b2  = (const float*)d_in[10];
    const float* W1  = (const float*)d_in[11];
    const float* bf1 = (const float*)d_in[12];
    const float* W2  = (const float*)d_in[13];
    const float* bf2 = (const float*)d_in[14];
    float* out = (float*)d_out;

    float *Q, *AO, *X, *Y, *Hd;
    __nv_bfloat162 *K2, *V2;
    cudaGetSymbolAddress((void**)&Q,  g_Q);
    cudaGetSymbolAddress((void**)&K2, g_K2);
    cudaGetSymbolAddress((void**)&V2, g_V2);
    cudaGetSymbolAddress((void**)&AO, g_AO);
    cudaGetSymbolAddress((void**)&X,  g_X);
    cudaGetSymbolAddress((void**)&Y,  g_Y);
    cudaGetSymbolAddress((void**)&Hd, g_Hid);

    dim3 blk(256);
    const long chw  = (long)C3 * HW;      // NCHW batch stride / bf16 elements
    const long c1hw = (long)C1 * HW;
    const long xstr = (long)HW * C3;      // NHWC batch stride

    // projections (Q: NCHW fp32; K/V: packed bf16 [cpair][HW])
    gemm_tc<0,0,0,0,0,0><<<dim3(313, 2, BSZ), blk>>>(
        Wq, F_lidar, nullptr, nullptr, nullptr, Q, C3, HW, C1, 0, 0, c1hw, chw);
    gemm_tc<0,0,0,0,0,1><<<dim3(313, 2, BSZ), blk>>>(
        Wk, F_cam, nullptr, nullptr, nullptr, (float*)K2, C3, HW, C3, 0, 0, chw, chw);
    gemm_tc<0,0,0,0,0,1><<<dim3(313, 2, BSZ), blk>>>(
        Wv, F_cam, nullptr, nullptr, nullptr, (float*)V2, C3, HW, C3, 0, 0, chw, chw);

    // attention (NHWC out), two-phase + f32x2
    attn_kernel<<<dim3((HW + 127) / 128, NHEADS, BSZ), dim3(128)>>>(Q, K2, V2, AO);

    // X = [AO | F_lidar^T] @ [Wo^T ; Wr^T]  (concat-K fused GEMM, per batch)
    gemm_tc<2,1,0,0,0,0><<<dim3(2, 313, BSZ), blk>>>(
        AO, Wo, F_lidar, Wr, nullptr, X, HW, C3, C3 + C1, xstr, c1hw, 0, xstr);

    // LN1 in place
    ln_kernel<<<(BSZ * HW * 32 + 255) / 256, blk>>>(X, g1, b1, BSZ * HW);

    // FFN
    gemm_tc<0,0,0,1,1,0><<<dim3(8, 625, 1), blk>>>(
        X,  W1, nullptr, nullptr, bf1, Hd, BSZ * HW, CF, C3, 0, 0, 0, 0);
    gemm_tc<0,0,0,0,1,0><<<dim3(2, 625, 1), blk>>>(
        Hd, W2, nullptr, nullptr, bf2, Y,  BSZ * HW, C3, CF, 0, 0, 0, 0);

    // LN2(x+y) -> NCHW
    final_kernel<<<dim3(HW / 32, BSZ), blk>>>(X, Y, g2, b2, out);
}